// round 8
// baseline (speedup 1.0000x reference)
#include <cuda_runtime.h>
#include <cuda_fp16.h>
#include <mma.h>

using namespace nvcuda;
typedef unsigned long long ull;

#define Bn 4
#define Hh 128
#define Wwidth 128
#define HW (128*128)

// ---------------- packed fp32x2 helpers ------------------------------------
__device__ __forceinline__ ull pk(float lo, float hi) {
    ull r; asm("mov.b64 %0, {%1,%2};" : "=l"(r) : "f"(lo), "f"(hi)); return r;
}
__device__ __forceinline__ void upk(ull v, float& lo, float& hi) {
    asm("mov.b64 {%0,%1}, %2;" : "=f"(lo), "=f"(hi) : "l"(v));
}
__device__ __forceinline__ ull ffma2(ull a, ull b, ull c) {
    ull d; asm("fma.rn.f32x2 %0, %1, %2, %3;" : "=l"(d) : "l"(a), "l"(b), "l"(c)); return d;
}

// -------- scratch --------
__device__ float  g_om [Bn*216*HW];            // conv_om raw (fp32 NCHW)
__device__ float  g_em [Bn*72*HW];             // sigmoid(conv em2) fp32 NCHW
// channel-interleaved fp16 planes: [b][chunk16][h][w][ci16]
__device__ __half g_xi [(size_t)Bn*64*HW];     // x      (deform sampling only)
__device__ __half g_si [(size_t)Bn*64*HW];     // share  (conv input + sampling)
__device__ __half g_ofi[(size_t)Bn*64*HW];     // offset_feat (conv input)
__device__ __half g_e1i[(size_t)Bn*64*HW];     // em1 output (conv input)
// packed fp16 weights [CoP][Ktot], K index = (chunk*9+tap)*16+ci
__device__ __half g_wom[256*576];
__device__ __half g_we1[64*1152];
__device__ __half g_we2[128*576];

// ---------------------------------------------------------------------------
// weight pack: w[Co][CIN][9] fp32 -> fp16 [CoP][CIN*9] with K reorder
// ---------------------------------------------------------------------------
__global__ void pack_w_kernel(const float* __restrict__ w, __half* __restrict__ d,
                              int Co, int CoP, int CIN)
{
    int idx = blockIdx.x * 256 + threadIdx.x;
    int Ktot = CIN * 9;
    if (idx >= CoP * Ktot) return;
    int co = idx / Ktot, k = idx % Ktot;
    int chunk = k / 144, rem = k % 144, tap = rem / 16, ci = rem % 16;
    int cin = chunk * 16 + ci;
    float v = (co < Co) ? w[((size_t)co * CIN + cin) * 9 + tap] : 0.f;
    d[idx] = __float2half_rn(v);
}

// ---------------------------------------------------------------------------
// input transpose: NCHW fp32 -> [b][chunk][h][w][ci16] fp16
// ---------------------------------------------------------------------------
__global__ void __launch_bounds__(128) split_t_kernel(
    const float* __restrict__ in, __half* __restrict__ o)
{
    const int px = threadIdx.x;
    const int h = blockIdx.x, chunk = blockIdx.y, b = blockIdx.z;
    const float* src = in + (size_t)(b * 64 + chunk * 16) * HW + h * Wwidth + px;
    __half hv[16];
    #pragma unroll
    for (int ci = 0; ci < 16; ci++) hv[ci] = __float2half_rn(src[(size_t)ci * HW]);
    size_t off = (((size_t)(b * 4 + chunk) * Hh + h) * Wwidth + px) * 16;
    ((uint4*)(o + off))[0] = ((const uint4*)hv)[0];
    ((uint4*)(o + off))[1] = ((const uint4*)hv)[1];
}

// ---------------------------------------------------------------------------
// Tensor-core implicit-GEMM 3x3 conv, pad=1, fp16 single-pass (fp32 accum).
// Block = TWO output rows x 128 px x 64 co. 512 threads = 16 warps.
// ---------------------------------------------------------------------------
#define XSZ2 (4*132*16)                 // halves, 2-row input tile
#define SMEM_CONV (XSZ2*2 + 64*144*2)   // 35328 B

template<int CHUNKS, int C0CHUNKS, int ACT>
__global__ void __launch_bounds__(512) conv2_kernel(
    const __half* __restrict__ x0, const __half* __restrict__ x1,
    const __half* __restrict__ wA, const float* __restrict__ bias,
    float* __restrict__ outF, __half* __restrict__ outH, int Co)
{
    extern __shared__ __align__(16) char smem_raw[];
    __half* s_x = (__half*)smem_raw;                    // [4][132][16]
    __half* s_w = (__half*)(smem_raw + XSZ2 * 2);       // [64][144]
    float*  sEp = (float*)smem_raw;                     // [64][136] (aliased, per row)

    const int tid = threadIdx.x;
    const int h2 = blockIdx.x, b = blockIdx.y, coTile = blockIdx.z;
    const int h0 = h2 * 2;
    const int warp = tid >> 5;
    const int rowSub = warp >> 3;
    const int coSub  = (warp >> 2) & 1;
    const int nSub   = warp & 3;
    const int Ktot   = CHUNKS * 144;

    wmma::fragment<wmma::accumulator, 16, 16, 16, float> acc[2][2];
    #pragma unroll
    for (int cf = 0; cf < 2; cf++)
        #pragma unroll
        for (int nf = 0; nf < 2; nf++) wmma::fill_fragment(acc[cf][nf], 0.f);

    if (tid < 32) {
        int r = tid >> 3, q = tid & 7;
        const int cols[4] = {0, 129, 130, 131};
        int scol = cols[q >> 1];
        uint4 z = {0, 0, 0, 0};
        ((uint4*)(s_x + (r * 132 + scol) * 16))[q & 1] = z;
    }

    for (int chunk = 0; chunk < CHUNKS; chunk++) {
        const __half* base;
        if (chunk < C0CHUNKS)
            base = x0 + ((size_t)b * C0CHUNKS + chunk) * HW * 16;
        else
            base = x1 + ((size_t)b * (CHUNKS - C0CHUNKS) + (chunk - C0CHUNKS)) * HW * 16;
        for (int u = tid; u < 1024; u += 512) {
            int r = u >> 8, c = u & 255;
            int row = h0 - 1 + r;
            uint4 v = {0, 0, 0, 0};
            if (row >= 0 && row < Hh)
                v = *(const uint4*)(base + (size_t)row * 2048 + c * 8);
            *(uint4*)(s_x + (r * 132 + 1) * 16 + c * 8) = v;
        }
        for (int u = tid; u < 1152; u += 512) {
            int co = u / 18, c = u - co * 18;
            *(uint4*)(s_w + co * 144 + c * 8) =
                *(const uint4*)(wA + (size_t)(coTile * 64 + co) * Ktot + chunk * 144 + c * 8);
        }
        __syncthreads();

        #pragma unroll
        for (int tap = 0; tap < 9; tap++) {
            const int dr = tap / 3, dc = tap % 3;
            wmma::fragment<wmma::matrix_a, 16, 16, 16, __half, wmma::row_major> af[2];
            #pragma unroll
            for (int cf = 0; cf < 2; cf++)
                wmma::load_matrix_sync(af[cf], s_w + (coSub * 32 + cf * 16) * 144 + tap * 16, 144);
            wmma::fragment<wmma::matrix_b, 16, 16, 16, __half, wmma::col_major> bfr[2];
            #pragma unroll
            for (int nf = 0; nf < 2; nf++) {
                int scol = nSub * 32 + nf * 16 + dc;
                wmma::load_matrix_sync(bfr[nf], s_x + ((rowSub + dr) * 132 + scol) * 16, 16);
            }
            #pragma unroll
            for (int cf = 0; cf < 2; cf++)
                #pragma unroll
                for (int nf = 0; nf < 2; nf++)
                    wmma::mma_sync(acc[cf][nf], af[cf], bfr[nf], acc[cf][nf]);
        }
        __syncthreads();
    }

    #pragma unroll
    for (int r = 0; r < 2; r++) {
        if (rowSub == r) {
            #pragma unroll
            for (int cf = 0; cf < 2; cf++)
                #pragma unroll
                for (int nf = 0; nf < 2; nf++)
                    wmma::store_matrix_sync(
                        sEp + (coSub * 32 + cf * 16) * 136 + (nSub * 32 + nf * 16),
                        acc[cf][nf], 136, wmma::mem_row_major);
        }
        __syncthreads();

        const int h = h0 + r;
        const int px = tid & 127;
        if (ACT == 1) {
            int ch = tid >> 7;
            __half hv[16];
            #pragma unroll
            for (int ci = 0; ci < 16; ci++) {
                int co = ch * 16 + ci;
                float v = sEp[co * 136 + px] + bias[co];
                v = (v >= 0.f) ? v : 0.1f * v;
                hv[ci] = __float2half_rn(v);
            }
            size_t o = (((size_t)(b * 4 + ch) * Hh + h) * Wwidth + px) * 16;
            ((uint4*)(outH + o))[0] = ((const uint4*)hv)[0];
            ((uint4*)(outH + o))[1] = ((const uint4*)hv)[1];
        } else {
            for (int co = tid >> 7; co < 64; co += 4) {
                int oc = coTile * 64 + co;
                if (oc < Co) {
                    float v = sEp[co * 136 + px] + bias[oc];
                    if (ACT == 2) v = 1.f / (1.f + __expf(-v));
                    outF[((size_t)b * Co + oc) * HW + h * Wwidth + px] = v;
                }
            }
        }
        __syncthreads();
    }
}

// ---------------------------------------------------------------------------
// Both deformable convs: warps 0-3 -> x_deform, warps 4-7 -> share_deform.
// Offsets/masks/em staged into SMEM via coalesced block loads (sigmoid applied
// once at staging). Gathers sample the channel-interleaved fp16 planes.
// ---------------------------------------------------------------------------
__global__ void __launch_bounds__(256) deform_kernel(
    const float* __restrict__ w_dc, const float* __restrict__ b_dc,
    float* __restrict__ out)
{
    __shared__ __align__(16) float s_om[36][128]; // [0..17] dy/dx, [18..26] sig(mask), [27..35] em
    __shared__ __align__(16) float s_w[8][9][8];
    __shared__ float s_b[8];

    const int tid  = threadIdx.x;
    const int half = tid >> 7;
    const int w    = tid & 127;
    const int h    = blockIdx.x;
    const int bg   = blockIdx.y;
    const int b    = bg >> 3, g = bg & 7;

    for (int e = tid; e < 576; e += 256) {
        int c = e / 72, r = e % 72;
        int kk = r / 8, co = r % 8;
        s_w[c][kk][co] = w_dc[((size_t)(g * 8 + co) * 8 + c) * 9 + kk];
    }
    if (tid < 8) s_b[tid] = b_dc[g * 8 + tid];

    // stage offsets / sigmoid(mask) / em for this (b, g, h): 36 ch x 128 px
    {
        const size_t rowOff = (size_t)h * Wwidth;
        for (int u = tid; u < 36 * 128; u += 256) {
            int r = u >> 7, c = u & 127;
            const float* srcp;
            if (r < 18)
                srcp = g_om + ((size_t)b * 216 + g * 18 + r) * HW;
            else if (r < 27)
                srcp = g_om + ((size_t)b * 216 + 144 + g * 9 + (r - 18)) * HW;
            else
                srcp = g_em + ((size_t)b * 72 + g * 9 + (r - 27)) * HW;
            float v = srcp[rowOff + c];
            if (r >= 18 && r < 27) v = 1.f / (1.f + __expf(-v));
            s_om[r][c] = v;
        }
    }
    __syncthreads();

    const __half* src = (half ? g_si : g_xi)
                        + ((size_t)(b * 4 + (g >> 1)) * HW) * 16 + (g & 1) * 8;

    ull acc[4];
    #pragma unroll
    for (int j = 0; j < 4; j++) acc[j] = 0ull;

    #pragma unroll
    for (int kk = 0; kk < 9; kk++) {
        const int kh = kk / 3, kw = kk % 3;
        float dy = s_om[2 * kk][w];
        float dx = s_om[2 * kk + 1][w];
        float mask = half ? s_om[27 + kk][w] : s_om[18 + kk][w];

        float py = (float)(h - 1 + kh) + dy;
        float px = (float)(w - 1 + kw) + dx;
        float fy = floorf(py), fx = floorf(px);
        float ly = py - fy, lx = px - fx;
        int y0 = (int)fy, x0 = (int)fx;
        int y1 = y0 + 1, x1 = x0 + 1;

        float w00 = (1.f - ly) * (1.f - lx);
        float w01 = (1.f - ly) * lx;
        float w10 = ly * (1.f - lx);
        float w11 = ly * lx;
        if (y0 < 0 || y0 >= Hh)     { w00 = 0.f; w01 = 0.f; }
        if (y1 < 0 || y1 >= Hh)     { w10 = 0.f; w11 = 0.f; }
        if (x0 < 0 || x0 >= Wwidth) { w00 = 0.f; w10 = 0.f; }
        if (x1 < 0 || x1 >= Wwidth) { w01 = 0.f; w11 = 0.f; }

        int cy0 = min(max(y0, 0), Hh - 1),     cy1 = min(max(y1, 0), Hh - 1);
        int cx0 = min(max(x0, 0), Wwidth - 1), cx1 = min(max(x1, 0), Wwidth - 1);
        int i00 = (cy0 * Wwidth + cx0) * 16, i01 = (cy0 * Wwidth + cx1) * 16;
        int i10 = (cy1 * Wwidth + cx0) * 16, i11 = (cy1 * Wwidth + cx1) * 16;

        float4 r00 = *(const float4*)(src + i00);
        float4 r01 = *(const float4*)(src + i01);
        float4 r10 = *(const float4*)(src + i10);
        float4 r11 = *(const float4*)(src + i11);
        const __half2* h00 = (const __half2*)&r00;
        const __half2* h01 = (const __half2*)&r01;
        const __half2* h10 = (const __half2*)&r10;
        const __half2* h11 = (const __half2*)&r11;

        float vv[8];
        #pragma unroll
        for (int j2 = 0; j2 < 4; j2++) {
            float2 f00 = __half22float2(h00[j2]);
            float2 f01 = __half22float2(h01[j2]);
            float2 f10 = __half22float2(h10[j2]);
            float2 f11 = __half22float2(h11[j2]);
            vv[2 * j2]     = (w00 * f00.x + w01 * f01.x + w10 * f10.x + w11 * f11.x) * mask;
            vv[2 * j2 + 1] = (w00 * f00.y + w01 * f01.y + w10 * f10.y + w11 * f11.y) * mask;
        }

        #pragma unroll
        for (int c = 0; c < 8; c++) {
            ull xs = pk(vv[c], vv[c]);
            #pragma unroll
            for (int j = 0; j < 4; j++) {
                ull wp = *(const ull*)&s_w[c][kk][2 * j];
                acc[j] = ffma2(xs, wp, acc[j]);
            }
        }
    }

    float* ob = out + (size_t)half * Bn * 64 * HW + (size_t)(b * 64 + g * 8) * HW
                    + h * Wwidth + w;
    #pragma unroll
    for (int j = 0; j < 4; j++) {
        float v0, v1;
        upk(acc[j], v0, v1);
        ob[(size_t)(2 * j) * HW]     = v0 + s_b[2 * j];
        ob[(size_t)(2 * j + 1) * HW] = v1 + s_b[2 * j + 1];
    }
}

// ---------------------------------------------------------------------------
extern "C" void kernel_launch(void* const* d_in, const int* in_sizes, int n_in,
                              void* d_out, int out_size)
{
    const float* x      = (const float*)d_in[0];
    const float* share  = (const float*)d_in[1];
    const float* offF   = (const float*)d_in[2];
    const float* w_om   = (const float*)d_in[3];
    const float* b_om   = (const float*)d_in[4];
    const float* w_em1  = (const float*)d_in[5];
    const float* b_em1  = (const float*)d_in[6];
    const float* w_em2  = (const float*)d_in[7];
    const float* b_em2  = (const float*)d_in[8];
    const float* w_dc   = (const float*)d_in[9];
    const float* b_dc   = (const float*)d_in[10];
    float* out = (float*)d_out;

    float *pom, *pem;
    __half *pxi, *psi, *pofi, *pe1i, *pwom, *pwe1, *pwe2;
    cudaGetSymbolAddress((void**)&pom,  g_om);
    cudaGetSymbolAddress((void**)&pem,  g_em);
    cudaGetSymbolAddress((void**)&pxi,  g_xi);
    cudaGetSymbolAddress((void**)&psi,  g_si);
    cudaGetSymbolAddress((void**)&pofi, g_ofi);
    cudaGetSymbolAddress((void**)&pe1i, g_e1i);
    cudaGetSymbolAddress((void**)&pwom, g_wom);
    cudaGetSymbolAddress((void**)&pwe1, g_we1);
    cudaGetSymbolAddress((void**)&pwe2, g_we2);

    cudaFuncSetAttribute(conv2_kernel<4, 4, 0>,
                         cudaFuncAttributeMaxDynamicSharedMemorySize, SMEM_CONV);
    cudaFuncSetAttribute(conv2_kernel<8, 4, 1>,
                         cudaFuncAttributeMaxDynamicSharedMemorySize, SMEM_CONV);
    cudaFuncSetAttribute(conv2_kernel<4, 4, 2>,
                         cudaFuncAttributeMaxDynamicSharedMemorySize, SMEM_CONV);

    // ncu profiles the 6th launch -> conv_om there
    pack_w_kernel<<<(256 * 576 + 255) / 256, 256>>>(w_om, pwom, 216, 256, 64);   // 1
    split_t_kernel<<<dim3(128, 4, 4), 128>>>(offF, pofi);                         // 2
    pack_w_kernel<<<(64 * 1152 + 255) / 256, 256>>>(w_em1, pwe1, 64, 64, 128);   // 3
    split_t_kernel<<<dim3(128, 4, 4), 128>>>(share, psi);                         // 4
    split_t_kernel<<<dim3(128, 4, 4), 128>>>(x, pxi);                             // 5
    conv2_kernel<4, 4, 0><<<dim3(64, 4, 4), 512, SMEM_CONV>>>(                    // 6: om
        pofi, pofi, pwom, b_om, pom, nullptr, 216);
    pack_w_kernel<<<(128 * 576 + 255) / 256, 256>>>(w_em2, pwe2, 72, 128, 64);   // 7
    conv2_kernel<8, 4, 1><<<dim3(64, 4, 1), 512, SMEM_CONV>>>(                    // 8: em1
        psi, pofi, pwe1, b_em1, nullptr, pe1i, 64);
    conv2_kernel<4, 4, 2><<<dim3(64, 4, 2), 512, SMEM_CONV>>>(                    // 9: em2
        pe1i, pe1i, pwe2, b_em2, pem, nullptr, 72);
    deform_kernel<<<dim3(128, 32), 256>>>(w_dc, b_dc, out);                       // 10

    (void)in_sizes; (void)n_in; (void)out_size;
}

// round 9
// speedup vs baseline: 1.1110x; 1.1110x over previous
#include <cuda_runtime.h>
#include <cuda_fp16.h>
#include <mma.h>

using namespace nvcuda;
typedef unsigned long long ull;

#define Bn 4
#define Hh 128
#define Wwidth 128
#define HW (128*128)

// ---------------- packed fp32x2 helpers ------------------------------------
__device__ __forceinline__ ull pk(float lo, float hi) {
    ull r; asm("mov.b64 %0, {%1,%2};" : "=l"(r) : "f"(lo), "f"(hi)); return r;
}
__device__ __forceinline__ void upk(ull v, float& lo, float& hi) {
    asm("mov.b64 {%0,%1}, %2;" : "=f"(lo), "=f"(hi) : "l"(v));
}
__device__ __forceinline__ ull ffma2(ull a, ull b, ull c) {
    ull d; asm("fma.rn.f32x2 %0, %1, %2, %3;" : "=l"(d) : "l"(a), "l"(b), "l"(c)); return d;
}

// -------- scratch --------
__device__ float  g_om [Bn*216*HW];            // conv_om raw (fp32 NCHW)
__device__ float  g_em [Bn*72*HW];             // sigmoid(conv em2) fp32 NCHW
// channel-interleaved fp16 planes: [b][chunk16][h][w][ci16]
__device__ __half g_xi [(size_t)Bn*64*HW];     // x      (deform sampling only)
__device__ __half g_si [(size_t)Bn*64*HW];     // share  (conv input + sampling)
__device__ __half g_ofi[(size_t)Bn*64*HW];     // offset_feat (conv input)
__device__ __half g_e1i[(size_t)Bn*64*HW];     // em1 output (conv input)
// packed fp16 weights [CoP][Ktot], K index = (chunk*9+tap)*16+ci
__device__ __half g_wom[256*576];
__device__ __half g_we1[64*1152];
__device__ __half g_we2[128*576];

// ---------------------------------------------------------------------------
// fused weight pack: all three weight tensors in one launch.
// blockIdx.y selects tensor. w[Co][CIN][9] fp32 -> fp16 [CoP][CIN*9], K reorder
// ---------------------------------------------------------------------------
__global__ void pack_all_kernel(const float* __restrict__ w0,
                                const float* __restrict__ w1,
                                const float* __restrict__ w2,
                                __half* __restrict__ d0,
                                __half* __restrict__ d1,
                                __half* __restrict__ d2)
{
    const int t = blockIdx.y;
    const float* w; __half* d; int Co, CoP, CIN;
    if (t == 0)      { w = w0; d = d0; Co = 216; CoP = 256; CIN = 64; }
    else if (t == 1) { w = w1; d = d1; Co = 64;  CoP = 64;  CIN = 128; }
    else             { w = w2; d = d2; Co = 72;  CoP = 128; CIN = 64; }

    int idx = blockIdx.x * 256 + threadIdx.x;
    int Ktot = CIN * 9;
    if (idx >= CoP * Ktot) return;
    int co = idx / Ktot, k = idx % Ktot;
    int chunk = k / 144, rem = k % 144, tap = rem / 16, ci = rem % 16;
    int cin = chunk * 16 + ci;
    float v = (co < Co) ? w[((size_t)co * CIN + cin) * 9 + tap] : 0.f;
    d[idx] = __float2half_rn(v);
}

// ---------------------------------------------------------------------------
// fused input transpose: NCHW fp32 -> [b][chunk][h][w][ci16] fp16, 3 tensors
// blockIdx.z = tensor*16 + b*4 + chunk
// ---------------------------------------------------------------------------
__global__ void __launch_bounds__(128) split_all_kernel(
    const float* __restrict__ in0, const float* __restrict__ in1,
    const float* __restrict__ in2,
    __half* __restrict__ o0, __half* __restrict__ o1, __half* __restrict__ o2)
{
    const int px = threadIdx.x;
    const int h = blockIdx.x;
    const int z = blockIdx.z;
    const int t = z >> 4;
    const int b = (z >> 2) & 3, chunk = z & 3;
    const float* in = (t == 0) ? in0 : (t == 1) ? in1 : in2;
    __half*      o  = (t == 0) ? o0  : (t == 1) ? o1  : o2;

    const float* src = in + (size_t)(b * 64 + chunk * 16) * HW + h * Wwidth + px;
    __half hv[16];
    #pragma unroll
    for (int ci = 0; ci < 16; ci++) hv[ci] = __float2half_rn(src[(size_t)ci * HW]);
    size_t off = (((size_t)(b * 4 + chunk) * Hh + h) * Wwidth + px) * 16;
    ((uint4*)(o + off))[0] = ((const uint4*)hv)[0];
    ((uint4*)(o + off))[1] = ((const uint4*)hv)[1];
}

// ---------------------------------------------------------------------------
// Tensor-core implicit-GEMM 3x3 conv, pad=1, fp16 single-pass (fp32 accum).
// Block = TWO output rows x 128 px x 64 co. 512 threads = 16 warps.
// ---------------------------------------------------------------------------
#define XSZ2 (4*132*16)                 // halves, 2-row input tile
#define SMEM_CONV (XSZ2*2 + 64*144*2)   // 35328 B

template<int CHUNKS, int C0CHUNKS, int ACT>
__global__ void __launch_bounds__(512) conv2_kernel(
    const __half* __restrict__ x0, const __half* __restrict__ x1,
    const __half* __restrict__ wA, const float* __restrict__ bias,
    float* __restrict__ outF, __half* __restrict__ outH, int Co)
{
    extern __shared__ __align__(16) char smem_raw[];
    __half* s_x = (__half*)smem_raw;                    // [4][132][16]
    __half* s_w = (__half*)(smem_raw + XSZ2 * 2);       // [64][144]
    float*  sEp = (float*)smem_raw;                     // [64][136] (aliased, per row)

    const int tid = threadIdx.x;
    const int h2 = blockIdx.x, b = blockIdx.y, coTile = blockIdx.z;
    const int h0 = h2 * 2;
    const int warp = tid >> 5;
    const int rowSub = warp >> 3;
    const int coSub  = (warp >> 2) & 1;
    const int nSub   = warp & 3;
    const int Ktot   = CHUNKS * 144;

    wmma::fragment<wmma::accumulator, 16, 16, 16, float> acc[2][2];
    #pragma unroll
    for (int cf = 0; cf < 2; cf++)
        #pragma unroll
        for (int nf = 0; nf < 2; nf++) wmma::fill_fragment(acc[cf][nf], 0.f);

    if (tid < 32) {
        int r = tid >> 3, q = tid & 7;
        const int cols[4] = {0, 129, 130, 131};
        int scol = cols[q >> 1];
        uint4 z = {0, 0, 0, 0};
        ((uint4*)(s_x + (r * 132 + scol) * 16))[q & 1] = z;
    }

    for (int chunk = 0; chunk < CHUNKS; chunk++) {
        const __half* base;
        if (chunk < C0CHUNKS)
            base = x0 + ((size_t)b * C0CHUNKS + chunk) * HW * 16;
        else
            base = x1 + ((size_t)b * (CHUNKS - C0CHUNKS) + (chunk - C0CHUNKS)) * HW * 16;
        for (int u = tid; u < 1024; u += 512) {
            int r = u >> 8, c = u & 255;
            int row = h0 - 1 + r;
            uint4 v = {0, 0, 0, 0};
            if (row >= 0 && row < Hh)
                v = *(const uint4*)(base + (size_t)row * 2048 + c * 8);
            *(uint4*)(s_x + (r * 132 + 1) * 16 + c * 8) = v;
        }
        for (int u = tid; u < 1152; u += 512) {
            int co = u / 18, c = u - co * 18;
            *(uint4*)(s_w + co * 144 + c * 8) =
                *(const uint4*)(wA + (size_t)(coTile * 64 + co) * Ktot + chunk * 144 + c * 8);
        }
        __syncthreads();

        #pragma unroll
        for (int tap = 0; tap < 9; tap++) {
            const int dr = tap / 3, dc = tap % 3;
            wmma::fragment<wmma::matrix_a, 16, 16, 16, __half, wmma::row_major> af[2];
            #pragma unroll
            for (int cf = 0; cf < 2; cf++)
                wmma::load_matrix_sync(af[cf], s_w + (coSub * 32 + cf * 16) * 144 + tap * 16, 144);
            wmma::fragment<wmma::matrix_b, 16, 16, 16, __half, wmma::col_major> bfr[2];
            #pragma unroll
            for (int nf = 0; nf < 2; nf++) {
                int scol = nSub * 32 + nf * 16 + dc;
                wmma::load_matrix_sync(bfr[nf], s_x + ((rowSub + dr) * 132 + scol) * 16, 16);
            }
            #pragma unroll
            for (int cf = 0; cf < 2; cf++)
                #pragma unroll
                for (int nf = 0; nf < 2; nf++)
                    wmma::mma_sync(acc[cf][nf], af[cf], bfr[nf], acc[cf][nf]);
        }
        __syncthreads();
    }

    #pragma unroll
    for (int r = 0; r < 2; r++) {
        if (rowSub == r) {
            #pragma unroll
            for (int cf = 0; cf < 2; cf++)
                #pragma unroll
                for (int nf = 0; nf < 2; nf++)
                    wmma::store_matrix_sync(
                        sEp + (coSub * 32 + cf * 16) * 136 + (nSub * 32 + nf * 16),
                        acc[cf][nf], 136, wmma::mem_row_major);
        }
        __syncthreads();

        const int h = h0 + r;
        const int px = tid & 127;
        if (ACT == 1) {
            int ch = tid >> 7;
            __half hv[16];
            #pragma unroll
            for (int ci = 0; ci < 16; ci++) {
                int co = ch * 16 + ci;
                float v = sEp[co * 136 + px] + bias[co];
                v = (v >= 0.f) ? v : 0.1f * v;
                hv[ci] = __float2half_rn(v);
            }
            size_t o = (((size_t)(b * 4 + ch) * Hh + h) * Wwidth + px) * 16;
            ((uint4*)(outH + o))[0] = ((const uint4*)hv)[0];
            ((uint4*)(outH + o))[1] = ((const uint4*)hv)[1];
        } else {
            for (int co = tid >> 7; co < 64; co += 4) {
                int oc = coTile * 64 + co;
                if (oc < Co) {
                    float v = sEp[co * 136 + px] + bias[oc];
                    if (ACT == 2) v = 1.f / (1.f + __expf(-v));
                    outF[((size_t)b * Co + oc) * HW + h * Wwidth + px] = v;
                }
            }
        }
        __syncthreads();
    }
}

// ---------------------------------------------------------------------------
// Both deformable convs (round-7 proven form): warps 0-3 -> x_deform,
// warps 4-7 -> share_deform. Per-tap om/em loads are warp-coalesced.
// ---------------------------------------------------------------------------
__global__ void __launch_bounds__(256) deform_kernel(
    const float* __restrict__ w_dc, const float* __restrict__ b_dc,
    float* __restrict__ out)
{
    __shared__ __align__(16) float s_w[8][9][8];
    __shared__ float s_b[8];

    const int tid  = threadIdx.x;
    const int half = tid >> 7;
    const int w    = tid & 127;
    const int h    = blockIdx.x;
    const int bg   = blockIdx.y;
    const int b    = bg >> 3, g = bg & 7;

    for (int e = tid; e < 576; e += 256) {
        int c = e / 72, r = e % 72;
        int kk = r / 8, co = r % 8;
        s_w[c][kk][co] = w_dc[((size_t)(g * 8 + co) * 8 + c) * 9 + kk];
    }
    if (tid < 8) s_b[tid] = b_dc[g * 8 + tid];
    __syncthreads();

    const int pix = h * Wwidth + w;
    const float* omB = g_om + (size_t)b * 216 * HW + pix;
    const float* emB = g_em + (size_t)b * 72 * HW + pix;
    const __half* src = (half ? g_si : g_xi)
                        + ((size_t)(b * 4 + (g >> 1)) * HW) * 16 + (g & 1) * 8;

    ull acc[4];
    #pragma unroll
    for (int j = 0; j < 4; j++) acc[j] = 0ull;

    #pragma unroll
    for (int kk = 0; kk < 9; kk++) {
        const int kh = kk / 3, kw = kk % 3;
        float dy = omB[(size_t)(g * 18 + 2 * kk) * HW];
        float dx = omB[(size_t)(g * 18 + 2 * kk + 1) * HW];
        float mask;
        if (half == 0) {
            float mz = omB[(size_t)(144 + g * 9 + kk) * HW];
            mask = 1.f / (1.f + __expf(-mz));
        } else {
            mask = emB[(size_t)(g * 9 + kk) * HW];
        }

        float py = (float)(h - 1 + kh) + dy;
        float px = (float)(w - 1 + kw) + dx;
        float fy = floorf(py), fx = floorf(px);
        float ly = py - fy, lx = px - fx;
        int y0 = (int)fy, x0 = (int)fx;
        int y1 = y0 + 1, x1 = x0 + 1;

        float w00 = (1.f - ly) * (1.f - lx);
        float w01 = (1.f - ly) * lx;
        float w10 = ly * (1.f - lx);
        float w11 = ly * lx;
        if (y0 < 0 || y0 >= Hh)     { w00 = 0.f; w01 = 0.f; }
        if (y1 < 0 || y1 >= Hh)     { w10 = 0.f; w11 = 0.f; }
        if (x0 < 0 || x0 >= Wwidth) { w00 = 0.f; w10 = 0.f; }
        if (x1 < 0 || x1 >= Wwidth) { w01 = 0.f; w11 = 0.f; }

        int cy0 = min(max(y0, 0), Hh - 1),     cy1 = min(max(y1, 0), Hh - 1);
        int cx0 = min(max(x0, 0), Wwidth - 1), cx1 = min(max(x1, 0), Wwidth - 1);
        int i00 = (cy0 * Wwidth + cx0) * 16, i01 = (cy0 * Wwidth + cx1) * 16;
        int i10 = (cy1 * Wwidth + cx0) * 16, i11 = (cy1 * Wwidth + cx1) * 16;

        float4 r00 = *(const float4*)(src + i00);
        float4 r01 = *(const float4*)(src + i01);
        float4 r10 = *(const float4*)(src + i10);
        float4 r11 = *(const float4*)(src + i11);
        const __half2* h00 = (const __half2*)&r00;
        const __half2* h01 = (const __half2*)&r01;
        const __half2* h10 = (const __half2*)&r10;
        const __half2* h11 = (const __half2*)&r11;

        float vv[8];
        #pragma unroll
        for (int j2 = 0; j2 < 4; j2++) {
            float2 f00 = __half22float2(h00[j2]);
            float2 f01 = __half22float2(h01[j2]);
            float2 f10 = __half22float2(h10[j2]);
            float2 f11 = __half22float2(h11[j2]);
            vv[2 * j2]     = (w00 * f00.x + w01 * f01.x + w10 * f10.x + w11 * f11.x) * mask;
            vv[2 * j2 + 1] = (w00 * f00.y + w01 * f01.y + w10 * f10.y + w11 * f11.y) * mask;
        }

        #pragma unroll
        for (int c = 0; c < 8; c++) {
            ull xs = pk(vv[c], vv[c]);
            #pragma unroll
            for (int j = 0; j < 4; j++) {
                ull wp = *(const ull*)&s_w[c][kk][2 * j];
                acc[j] = ffma2(xs, wp, acc[j]);
            }
        }
    }

    float* ob = out + (size_t)half * Bn * 64 * HW + (size_t)(b * 64 + g * 8) * HW + pix;
    #pragma unroll
    for (int j = 0; j < 4; j++) {
        float v0, v1;
        upk(acc[j], v0, v1);
        ob[(size_t)(2 * j) * HW]     = v0 + s_b[2 * j];
        ob[(size_t)(2 * j + 1) * HW] = v1 + s_b[2 * j + 1];
    }
}

// ---------------------------------------------------------------------------
extern "C" void kernel_launch(void* const* d_in, const int* in_sizes, int n_in,
                              void* d_out, int out_size)
{
    const float* x      = (const float*)d_in[0];
    const float* share  = (const float*)d_in[1];
    const float* offF   = (const float*)d_in[2];
    const float* w_om   = (const float*)d_in[3];
    const float* b_om   = (const float*)d_in[4];
    const float* w_em1  = (const float*)d_in[5];
    const float* b_em1  = (const float*)d_in[6];
    const float* w_em2  = (const float*)d_in[7];
    const float* b_em2  = (const float*)d_in[8];
    const float* w_dc   = (const float*)d_in[9];
    const float* b_dc   = (const float*)d_in[10];
    float* out = (float*)d_out;

    float *pom, *pem;
    __half *pxi, *psi, *pofi, *pe1i, *pwom, *pwe1, *pwe2;
    cudaGetSymbolAddress((void**)&pom,  g_om);
    cudaGetSymbolAddress((void**)&pem,  g_em);
    cudaGetSymbolAddress((void**)&pxi,  g_xi);
    cudaGetSymbolAddress((void**)&psi,  g_si);
    cudaGetSymbolAddress((void**)&pofi, g_ofi);
    cudaGetSymbolAddress((void**)&pe1i, g_e1i);
    cudaGetSymbolAddress((void**)&pwom, g_wom);
    cudaGetSymbolAddress((void**)&pwe1, g_we1);
    cudaGetSymbolAddress((void**)&pwe2, g_we2);

    cudaFuncSetAttribute(conv2_kernel<4, 4, 0>,
                         cudaFuncAttributeMaxDynamicSharedMemorySize, SMEM_CONV);
    cudaFuncSetAttribute(conv2_kernel<8, 4, 1>,
                         cudaFuncAttributeMaxDynamicSharedMemorySize, SMEM_CONV);
    cudaFuncSetAttribute(conv2_kernel<4, 4, 2>,
                         cudaFuncAttributeMaxDynamicSharedMemorySize, SMEM_CONV);

    // 6 launches; ncu profiles launch #6 -> deform_kernel
    pack_all_kernel<<<dim3(576, 3), 256>>>(w_om, w_em1, w_em2,                    // 1
                                           pwom, pwe1, pwe2);
    split_all_kernel<<<dim3(128, 1, 48), 128>>>(offF, share, x,                   // 2
                                                pofi, psi, pxi);
    conv2_kernel<4, 4, 0><<<dim3(64, 4, 4), 512, SMEM_CONV>>>(                    // 3: om
        pofi, pofi, pwom, b_om, pom, nullptr, 216);
    conv2_kernel<8, 4, 1><<<dim3(64, 4, 1), 512, SMEM_CONV>>>(                    // 4: em1
        psi, pofi, pwe1, b_em1, nullptr, pe1i, 64);
    conv2_kernel<4, 4, 2><<<dim3(64, 4, 2), 512, SMEM_CONV>>>(                    // 5: em2
        pe1i, pe1i, pwe2, b_em2, pem, nullptr, 72);
    deform_kernel<<<dim3(128, 32), 256>>>(w_dc, b_dc, out);                       // 6

    (void)in_sizes; (void)n_in; (void)out_size;
}